// round 5
// baseline (speedup 1.0000x reference)
#include <cuda_runtime.h>

#define NN 100000
#define NE 3200000
#define DIN 128
#define HD 16
#define SCAN_B 512
#define NSB ((NN + SCAN_B - 1) / SCAN_B)   // 196

// ---- scratch (static __device__, no allocation) ----
__device__ int    g_deg[NN];
__device__ float  g_dis[NN];
__device__ int    g_rowptr[NN + 1];
__device__ int    g_cursor[NN];
__device__ int    g_col[NE];
__device__ int    g_bsum[NSB];
__device__ float4 g_feat1[NN * 4];   // (x@W1) * dis[row], 16 floats/node
__device__ float4 g_feat2[NN * 4];   // (h1@W2) * dis[row]

__device__ __forceinline__ void fma4(float s, const float4 w, float4& a) {
    a.x = fmaf(s, w.x, a.x);
    a.y = fmaf(s, w.y, a.y);
    a.z = fmaf(s, w.z, a.z);
    a.w = fmaf(s, w.w, a.w);
}
__device__ __forceinline__ void add4(float4& a, const float4 v) {
    a.x += v.x; a.y += v.y; a.z += v.z; a.w += v.w;
}

// ---- CSR build ----
__global__ void k_zero() {
    int i = blockIdx.x * blockDim.x + threadIdx.x;
    if (i < NN) g_deg[i] = 0;
}

__global__ void k_count(const int4* __restrict__ dst4) {
    int e = blockIdx.x * blockDim.x + threadIdx.x;
    if (e < NE / 4) {
        int4 d = dst4[e];
        atomicAdd(&g_deg[d.x], 1);
        atomicAdd(&g_deg[d.y], 1);
        atomicAdd(&g_deg[d.z], 1);
        atomicAdd(&g_deg[d.w], 1);
    }
}

// per-block sum of degrees + dis[] computation (fused)
__global__ void k_scan_partial() {
    __shared__ int sh[SCAN_B];
    int i = blockIdx.x * SCAN_B + threadIdx.x;
    int d = (i < NN) ? g_deg[i] : 0;
    if (i < NN) g_dis[i] = rsqrtf((float)(d + 1));  // +1 self-loop
    sh[threadIdx.x] = d;
    __syncthreads();
    for (int off = SCAN_B / 2; off > 0; off >>= 1) {
        if (threadIdx.x < off) sh[threadIdx.x] += sh[threadIdx.x + off];
        __syncthreads();
    }
    if (threadIdx.x == 0) g_bsum[blockIdx.x] = sh[0];
}

// per-block exclusive scan; block offset computed in-kernel by reducing g_bsum[0..bid)
__global__ void k_scan_final() {
    __shared__ int sh[SCAN_B];
    __shared__ int red[SCAN_B];
    int tid = threadIdx.x;
    int i = blockIdx.x * SCAN_B + tid;
    int v = (i < NN) ? g_deg[i] : 0;
    sh[tid]  = v;
    red[tid] = (tid < blockIdx.x && tid < NSB) ? g_bsum[tid] : 0;
    __syncthreads();
    for (int off = SCAN_B / 2; off > 0; off >>= 1) {
        if (tid < off) red[tid] += red[tid + off];
        __syncthreads();
    }
    for (int off = 1; off < SCAN_B; off <<= 1) {
        int t = (tid >= off) ? sh[tid - off] : 0;
        __syncthreads();
        sh[tid] += t;
        __syncthreads();
    }
    int excl = red[0] + sh[tid] - v;  // exclusive prefix
    if (i < NN) { g_rowptr[i] = excl; g_cursor[i] = excl; }
    if (i == 0) g_rowptr[NN] = NE;
}

__global__ void k_fill(const int4* __restrict__ src4,
                       const int4* __restrict__ dst4) {
    int e = blockIdx.x * blockDim.x + threadIdx.x;
    if (e < NE / 4) {
        int4 s = src4[e];
        int4 d = dst4[e];
        g_col[atomicAdd(&g_cursor[d.x], 1)] = s.x;
        g_col[atomicAdd(&g_cursor[d.y], 1)] = s.y;
        g_col[atomicAdd(&g_cursor[d.z], 1)] = s.z;
        g_col[atomicAdd(&g_cursor[d.w], 1)] = s.w;
    }
}

// ---- gemm1: feat1[row] = (x[row] @ W1) * dis[row] ----
__global__ void k_gemm1(const float* __restrict__ x,
                        const float* __restrict__ W1) {
    __shared__ float4 w4[DIN * HD / 4];  // 512 float4 = 8KB
    for (int t = threadIdx.x; t < DIN * HD / 4; t += blockDim.x)
        w4[t] = ((const float4*)W1)[t];
    __syncthreads();

    int row = blockIdx.x * blockDim.x + threadIdx.x;
    if (row >= NN) return;

    float4 a0 = {0.f, 0.f, 0.f, 0.f}, a1 = a0, a2 = a0, a3 = a0;
    const float4* xr = (const float4*)(x + (size_t)row * DIN);
    #pragma unroll 8
    for (int kk = 0; kk < DIN / 4; kk++) {
        float4 xv = xr[kk];
        const float4* wr = &w4[kk * 16];
        fma4(xv.x, wr[0],  a0); fma4(xv.x, wr[1],  a1); fma4(xv.x, wr[2],  a2); fma4(xv.x, wr[3],  a3);
        fma4(xv.y, wr[4],  a0); fma4(xv.y, wr[5],  a1); fma4(xv.y, wr[6],  a2); fma4(xv.y, wr[7],  a3);
        fma4(xv.z, wr[8],  a0); fma4(xv.z, wr[9],  a1); fma4(xv.z, wr[10], a2); fma4(xv.z, wr[11], a3);
        fma4(xv.w, wr[12], a0); fma4(xv.w, wr[13], a1); fma4(xv.w, wr[14], a2); fma4(xv.w, wr[15], a3);
    }
    float s = g_dis[row];
    a0.x *= s; a0.y *= s; a0.z *= s; a0.w *= s;
    a1.x *= s; a1.y *= s; a1.z *= s; a1.w *= s;
    a2.x *= s; a2.y *= s; a2.z *= s; a2.w *= s;
    a3.x *= s; a3.y *= s; a3.z *= s; a3.w *= s;
    g_feat1[row * 4 + 0] = a0;
    g_feat1[row * 4 + 1] = a1;
    g_feat1[row * 4 + 2] = a2;
    g_feat1[row * 4 + 3] = a3;
}

// ---- fused: agg1 + relu + gemm2 + scale -> feat2 (one thread per node) ----
__global__ void k_agg1g2(const float* __restrict__ b1,
                         const float* __restrict__ W2) {
    __shared__ float4 w4[HD * HD / 4];  // 64 float4
    __shared__ float4 sb1[HD / 4];      // 4 float4
    for (int t = threadIdx.x; t < HD * HD / 4; t += blockDim.x)
        w4[t] = ((const float4*)W2)[t];
    if (threadIdx.x < HD / 4) sb1[threadIdx.x] = ((const float4*)b1)[threadIdx.x];
    __syncthreads();

    int node = blockIdx.x * blockDim.x + threadIdx.x;
    if (node >= NN) return;

    float4 a0 = g_feat1[node * 4 + 0];  // self-loop term
    float4 a1 = g_feat1[node * 4 + 1];
    float4 a2 = g_feat1[node * 4 + 2];
    float4 a3 = g_feat1[node * 4 + 3];
    int s = g_rowptr[node], e = g_rowptr[node + 1];
    for (int j = s; j < e; j++) {
        const float4* f = &g_feat1[g_col[j] * 4];
        add4(a0, f[0]); add4(a1, f[1]); add4(a2, f[2]); add4(a3, f[3]);
    }
    float ds = g_dis[node];
    float h[HD];
    {
        float4 bb;
        bb = sb1[0];
        h[0]  = fmaxf(fmaf(a0.x, ds, bb.x), 0.f); h[1]  = fmaxf(fmaf(a0.y, ds, bb.y), 0.f);
        h[2]  = fmaxf(fmaf(a0.z, ds, bb.z), 0.f); h[3]  = fmaxf(fmaf(a0.w, ds, bb.w), 0.f);
        bb = sb1[1];
        h[4]  = fmaxf(fmaf(a1.x, ds, bb.x), 0.f); h[5]  = fmaxf(fmaf(a1.y, ds, bb.y), 0.f);
        h[6]  = fmaxf(fmaf(a1.z, ds, bb.z), 0.f); h[7]  = fmaxf(fmaf(a1.w, ds, bb.w), 0.f);
        bb = sb1[2];
        h[8]  = fmaxf(fmaf(a2.x, ds, bb.x), 0.f); h[9]  = fmaxf(fmaf(a2.y, ds, bb.y), 0.f);
        h[10] = fmaxf(fmaf(a2.z, ds, bb.z), 0.f); h[11] = fmaxf(fmaf(a2.w, ds, bb.w), 0.f);
        bb = sb1[3];
        h[12] = fmaxf(fmaf(a3.x, ds, bb.x), 0.f); h[13] = fmaxf(fmaf(a3.y, ds, bb.y), 0.f);
        h[14] = fmaxf(fmaf(a3.z, ds, bb.z), 0.f); h[15] = fmaxf(fmaf(a3.w, ds, bb.w), 0.f);
    }
    float4 o0 = {0.f, 0.f, 0.f, 0.f}, o1 = o0, o2 = o0, o3 = o0;
    #pragma unroll
    for (int k = 0; k < HD; k++) {
        const float4* wr = &w4[k * 4];
        fma4(h[k], wr[0], o0); fma4(h[k], wr[1], o1);
        fma4(h[k], wr[2], o2); fma4(h[k], wr[3], o3);
    }
    o0.x *= ds; o0.y *= ds; o0.z *= ds; o0.w *= ds;
    o1.x *= ds; o1.y *= ds; o1.z *= ds; o1.w *= ds;
    o2.x *= ds; o2.y *= ds; o2.z *= ds; o2.w *= ds;
    o3.x *= ds; o3.y *= ds; o3.z *= ds; o3.w *= ds;
    g_feat2[node * 4 + 0] = o0;
    g_feat2[node * 4 + 1] = o1;
    g_feat2[node * 4 + 2] = o2;
    g_feat2[node * 4 + 3] = o3;
}

// ---- fused: agg2 + relu + linear head -> out (one thread per node) ----
__global__ void k_agg2h(const float* __restrict__ b2,
                        const float* __restrict__ Wl,
                        const float* __restrict__ bl,
                        float* __restrict__ out) {
    __shared__ float4 sb2[HD / 4];
    __shared__ float4 swl[HD / 4];
    __shared__ float  sbl;
    if (threadIdx.x < HD / 4) {
        sb2[threadIdx.x] = ((const float4*)b2)[threadIdx.x];
        swl[threadIdx.x] = ((const float4*)Wl)[threadIdx.x];
    }
    if (threadIdx.x == 0) sbl = bl[0];
    __syncthreads();

    int node = blockIdx.x * blockDim.x + threadIdx.x;
    if (node >= NN) return;

    float4 a0 = g_feat2[node * 4 + 0];  // self-loop term
    float4 a1 = g_feat2[node * 4 + 1];
    float4 a2 = g_feat2[node * 4 + 2];
    float4 a3 = g_feat2[node * 4 + 3];
    int s = g_rowptr[node], e = g_rowptr[node + 1];
    for (int j = s; j < e; j++) {
        const float4* f = &g_feat2[g_col[j] * 4];
        add4(a0, f[0]); add4(a1, f[1]); add4(a2, f[2]); add4(a3, f[3]);
    }
    float ds = g_dis[node];
    float acc = sbl;
    float4 bb, wl;
    bb = sb2[0]; wl = swl[0];
    acc += fmaxf(fmaf(a0.x, ds, bb.x), 0.f) * wl.x + fmaxf(fmaf(a0.y, ds, bb.y), 0.f) * wl.y
         + fmaxf(fmaf(a0.z, ds, bb.z), 0.f) * wl.z + fmaxf(fmaf(a0.w, ds, bb.w), 0.f) * wl.w;
    bb = sb2[1]; wl = swl[1];
    acc += fmaxf(fmaf(a1.x, ds, bb.x), 0.f) * wl.x + fmaxf(fmaf(a1.y, ds, bb.y), 0.f) * wl.y
         + fmaxf(fmaf(a1.z, ds, bb.z), 0.f) * wl.z + fmaxf(fmaf(a1.w, ds, bb.w), 0.f) * wl.w;
    bb = sb2[2]; wl = swl[2];
    acc += fmaxf(fmaf(a2.x, ds, bb.x), 0.f) * wl.x + fmaxf(fmaf(a2.y, ds, bb.y), 0.f) * wl.y
         + fmaxf(fmaf(a2.z, ds, bb.z), 0.f) * wl.z + fmaxf(fmaf(a2.w, ds, bb.w), 0.f) * wl.w;
    bb = sb2[3]; wl = swl[3];
    acc += fmaxf(fmaf(a3.x, ds, bb.x), 0.f) * wl.x + fmaxf(fmaf(a3.y, ds, bb.y), 0.f) * wl.y
         + fmaxf(fmaf(a3.z, ds, bb.z), 0.f) * wl.z + fmaxf(fmaf(a3.w, ds, bb.w), 0.f) * wl.w;
    out[node] = acc;
}

extern "C" void kernel_launch(void* const* d_in, const int* in_sizes, int n_in,
                              void* d_out, int out_size) {
    const float* x  = (const float*)d_in[0];
    const int*   ei = (const int*)d_in[1];    // int32 (JAX x64 disabled)
    const float* W1 = (const float*)d_in[2];
    const float* b1 = (const float*)d_in[3];
    const float* W2 = (const float*)d_in[4];
    const float* b2 = (const float*)d_in[5];
    const float* Wl = (const float*)d_in[6];
    const float* bl = (const float*)d_in[7];
    float* out = (float*)d_out;

    const int4* src4 = (const int4*)ei;          // edge_index[0]
    const int4* dst4 = (const int4*)(ei + NE);   // edge_index[1]

    k_zero        <<<(NN + 255) / 256, 256>>>();
    k_count       <<<(NE / 4 + 255) / 256, 256>>>(dst4);
    k_scan_partial<<<NSB, SCAN_B>>>();
    k_scan_final  <<<NSB, SCAN_B>>>();
    k_fill        <<<(NE / 4 + 255) / 256, 256>>>(src4, dst4);
    k_gemm1       <<<(NN + 255) / 256, 256>>>(x, W1);
    k_agg1g2      <<<(NN + 255) / 256, 256>>>(b1, W2);
    k_agg2h       <<<(NN + 255) / 256, 256>>>(b2, Wl, bl, out);
}

// round 6
// speedup vs baseline: 1.3424x; 1.3424x over previous
#include <cuda_runtime.h>

#define NN 100000
#define NE 3200000
#define DIN 128
#define HD 16
#define SCAN_B 512
#define NSB ((NN + SCAN_B - 1) / SCAN_B)   // 196

// ---- scratch (static __device__, no allocation) ----
__device__ int    g_deg[NN];
__device__ float  g_dis[NN];
__device__ int    g_rowptr[NN + 1];
__device__ int    g_cursor[NN];
__device__ int    g_col[NE];
__device__ int    g_bsum[NSB];
__device__ float4 g_feat1[NN * 4];   // (x@W1) * dis[row]
__device__ float4 g_h1[NN * 4];      // relu(layer1)
__device__ float4 g_feat2[NN * 4];   // (h1@W2) * dis[row]

__device__ __forceinline__ void fma4(float s, const float4 w, float4& a) {
    a.x = fmaf(s, w.x, a.x);
    a.y = fmaf(s, w.y, a.y);
    a.z = fmaf(s, w.z, a.z);
    a.w = fmaf(s, w.w, a.w);
}

// ---- CSR build ----
__global__ void k_zero() {
    int i = blockIdx.x * blockDim.x + threadIdx.x;
    if (i < NN) g_deg[i] = 0;
}

__global__ void k_count(const int4* __restrict__ dst4) {
    int e = blockIdx.x * blockDim.x + threadIdx.x;
    if (e < NE / 4) {
        int4 d = dst4[e];
        atomicAdd(&g_deg[d.x], 1);
        atomicAdd(&g_deg[d.y], 1);
        atomicAdd(&g_deg[d.z], 1);
        atomicAdd(&g_deg[d.w], 1);
    }
}

// per-block sum of degrees + dis[] computation (fused)
__global__ void k_scan_partial() {
    __shared__ int sh[SCAN_B];
    int i = blockIdx.x * SCAN_B + threadIdx.x;
    int d = (i < NN) ? g_deg[i] : 0;
    if (i < NN) g_dis[i] = rsqrtf((float)(d + 1));  // +1 self-loop
    sh[threadIdx.x] = d;
    __syncthreads();
    for (int off = SCAN_B / 2; off > 0; off >>= 1) {
        if (threadIdx.x < off) sh[threadIdx.x] += sh[threadIdx.x + off];
        __syncthreads();
    }
    if (threadIdx.x == 0) g_bsum[blockIdx.x] = sh[0];
}

// per-block exclusive scan; block offset computed in-kernel (no serial pass)
__global__ void k_scan_final() {
    __shared__ int sh[SCAN_B];
    __shared__ int red[SCAN_B];
    int tid = threadIdx.x;
    int i = blockIdx.x * SCAN_B + tid;
    int v = (i < NN) ? g_deg[i] : 0;
    sh[tid]  = v;
    red[tid] = (tid < blockIdx.x && tid < NSB) ? g_bsum[tid] : 0;
    __syncthreads();
    for (int off = SCAN_B / 2; off > 0; off >>= 1) {
        if (tid < off) red[tid] += red[tid + off];
        __syncthreads();
    }
    for (int off = 1; off < SCAN_B; off <<= 1) {
        int t = (tid >= off) ? sh[tid - off] : 0;
        __syncthreads();
        sh[tid] += t;
        __syncthreads();
    }
    int excl = red[0] + sh[tid] - v;  // exclusive prefix
    if (i < NN) { g_rowptr[i] = excl; g_cursor[i] = excl; }
    if (i == 0) g_rowptr[NN] = NE;
}

__global__ void k_fill(const int4* __restrict__ src4,
                       const int4* __restrict__ dst4) {
    int e = blockIdx.x * blockDim.x + threadIdx.x;
    if (e < NE / 4) {
        int4 s = src4[e];
        int4 d = dst4[e];
        g_col[atomicAdd(&g_cursor[d.x], 1)] = s.x;
        g_col[atomicAdd(&g_cursor[d.y], 1)] = s.y;
        g_col[atomicAdd(&g_cursor[d.z], 1)] = s.z;
        g_col[atomicAdd(&g_cursor[d.w], 1)] = s.w;
    }
}

// ---- gemm1: feat1[row] = (x[row] @ W1) * dis[row] ----
__global__ void k_gemm1(const float* __restrict__ x,
                        const float* __restrict__ W1) {
    __shared__ float4 w4[DIN * HD / 4];  // 512 float4 = 8KB
    for (int t = threadIdx.x; t < DIN * HD / 4; t += blockDim.x)
        w4[t] = ((const float4*)W1)[t];
    __syncthreads();

    int row = blockIdx.x * blockDim.x + threadIdx.x;
    if (row >= NN) return;

    float4 a0 = {0.f, 0.f, 0.f, 0.f}, a1 = a0, a2 = a0, a3 = a0;
    const float4* xr = (const float4*)(x + (size_t)row * DIN);
    #pragma unroll 8
    for (int kk = 0; kk < DIN / 4; kk++) {
        float4 xv = xr[kk];
        const float4* wr = &w4[kk * 16];
        fma4(xv.x, wr[0],  a0); fma4(xv.x, wr[1],  a1); fma4(xv.x, wr[2],  a2); fma4(xv.x, wr[3],  a3);
        fma4(xv.y, wr[4],  a0); fma4(xv.y, wr[5],  a1); fma4(xv.y, wr[6],  a2); fma4(xv.y, wr[7],  a3);
        fma4(xv.z, wr[8],  a0); fma4(xv.z, wr[9],  a1); fma4(xv.z, wr[10], a2); fma4(xv.z, wr[11], a3);
        fma4(xv.w, wr[12], a0); fma4(xv.w, wr[13], a1); fma4(xv.w, wr[14], a2); fma4(xv.w, wr[15], a3);
    }
    float s = g_dis[row];
    a0.x *= s; a0.y *= s; a0.z *= s; a0.w *= s;
    a1.x *= s; a1.y *= s; a1.z *= s; a1.w *= s;
    a2.x *= s; a2.y *= s; a2.z *= s; a2.w *= s;
    a3.x *= s; a3.y *= s; a3.z *= s; a3.w *= s;
    g_feat1[row * 4 + 0] = a0;
    g_feat1[row * 4 + 1] = a1;
    g_feat1[row * 4 + 2] = a2;
    g_feat1[row * 4 + 3] = a3;
}

// ---- aggregation layer 1 (4 lanes per node): h1 = relu(dis*(self+sum) + b1) ----
__global__ void k_agg1(const float* __restrict__ b1) {
    int t = blockIdx.x * blockDim.x + threadIdx.x;
    int node = t >> 2, q = t & 3;
    if (node >= NN) return;

    float4 acc = g_feat1[node * 4 + q];  // self loop term
    int s = g_rowptr[node], e = g_rowptr[node + 1];
    for (int j = s; j < e; j++) {
        int c = g_col[j];
        float4 v = g_feat1[c * 4 + q];
        acc.x += v.x; acc.y += v.y; acc.z += v.z; acc.w += v.w;
    }
    float ds = g_dis[node];
    float4 bb = ((const float4*)b1)[q];
    float4 h;
    h.x = fmaxf(fmaf(acc.x, ds, bb.x), 0.f);
    h.y = fmaxf(fmaf(acc.y, ds, bb.y), 0.f);
    h.z = fmaxf(fmaf(acc.z, ds, bb.z), 0.f);
    h.w = fmaxf(fmaf(acc.w, ds, bb.w), 0.f);
    g_h1[node * 4 + q] = h;
}

// ---- gemm2: feat2[row] = (h1[row] @ W2) * dis[row] ----
__global__ void k_gemm2(const float* __restrict__ W2) {
    __shared__ float4 w4[HD * HD / 4];  // 64 float4
    for (int t = threadIdx.x; t < HD * HD / 4; t += blockDim.x)
        w4[t] = ((const float4*)W2)[t];
    __syncthreads();

    int row = blockIdx.x * blockDim.x + threadIdx.x;
    if (row >= NN) return;

    float4 h0 = g_h1[row * 4 + 0];
    float4 h1 = g_h1[row * 4 + 1];
    float4 h2 = g_h1[row * 4 + 2];
    float4 h3 = g_h1[row * 4 + 3];
    float hv[HD] = {h0.x, h0.y, h0.z, h0.w, h1.x, h1.y, h1.z, h1.w,
                    h2.x, h2.y, h2.z, h2.w, h3.x, h3.y, h3.z, h3.w};

    float4 a0 = {0.f, 0.f, 0.f, 0.f}, a1 = a0, a2 = a0, a3 = a0;
    #pragma unroll
    for (int k = 0; k < HD; k++) {
        float s = hv[k];
        const float4* wr = &w4[k * 4];
        fma4(s, wr[0], a0); fma4(s, wr[1], a1); fma4(s, wr[2], a2); fma4(s, wr[3], a3);
    }
    float s = g_dis[row];
    a0.x *= s; a0.y *= s; a0.z *= s; a0.w *= s;
    a1.x *= s; a1.y *= s; a1.z *= s; a1.w *= s;
    a2.x *= s; a2.y *= s; a2.z *= s; a2.w *= s;
    a3.x *= s; a3.y *= s; a3.z *= s; a3.w *= s;
    g_feat2[row * 4 + 0] = a0;
    g_feat2[row * 4 + 1] = a1;
    g_feat2[row * 4 + 2] = a2;
    g_feat2[row * 4 + 3] = a3;
}

// ---- aggregation layer 2 + fused linear head (4 lanes per node) ----
// No early return: out-of-range lanes clamp to node NN-1 so every warp is fully
// converged at the shuffle (mask 0xffffffff is then valid); store is predicated.
__global__ void k_agg2h(const float* __restrict__ b2,
                        const float* __restrict__ Wl,
                        const float* __restrict__ bl,
                        float* __restrict__ out) {
    int t = blockIdx.x * blockDim.x + threadIdx.x;
    int node0 = t >> 2, q = t & 3;
    int node = node0 < NN ? node0 : NN - 1;

    float4 acc = g_feat2[node * 4 + q];  // self loop
    int s = g_rowptr[node], e = g_rowptr[node + 1];
    for (int j = s; j < e; j++) {
        int c = g_col[j];
        float4 v = g_feat2[c * 4 + q];
        acc.x += v.x; acc.y += v.y; acc.z += v.z; acc.w += v.w;
    }
    float ds = g_dis[node];
    float4 bb = ((const float4*)b2)[q];
    float4 wl = ((const float4*)Wl)[q];
    float p = fmaxf(fmaf(acc.x, ds, bb.x), 0.f) * wl.x
            + fmaxf(fmaf(acc.y, ds, bb.y), 0.f) * wl.y
            + fmaxf(fmaf(acc.z, ds, bb.z), 0.f) * wl.z
            + fmaxf(fmaf(acc.w, ds, bb.w), 0.f) * wl.w;
    // reduce across the 4-lane group
    p += __shfl_xor_sync(0xffffffffu, p, 1, 4);
    p += __shfl_xor_sync(0xffffffffu, p, 2, 4);
    if (q == 0 && node0 < NN) out[node0] = p + bl[0];
}

extern "C" void kernel_launch(void* const* d_in, const int* in_sizes, int n_in,
                              void* d_out, int out_size) {
    const float* x  = (const float*)d_in[0];
    const int*   ei = (const int*)d_in[1];    // int32 (JAX x64 disabled)
    const float* W1 = (const float*)d_in[2];
    const float* b1 = (const float*)d_in[3];
    const float* W2 = (const float*)d_in[4];
    const float* b2 = (const float*)d_in[5];
    const float* Wl = (const float*)d_in[6];
    const float* bl = (const float*)d_in[7];
    float* out = (float*)d_out;

    const int4* src4 = (const int4*)ei;          // edge_index[0]
    const int4* dst4 = (const int4*)(ei + NE);   // edge_index[1]

    k_zero        <<<(NN + 255) / 256, 256>>>();
    k_count       <<<(NE / 4 + 255) / 256, 256>>>(dst4);
    k_scan_partial<<<NSB, SCAN_B>>>();
    k_scan_final  <<<NSB, SCAN_B>>>();
    k_fill        <<<(NE / 4 + 255) / 256, 256>>>(src4, dst4);
    k_gemm1       <<<(NN + 255) / 256, 256>>>(x, W1);
    k_agg1        <<<(NN * 4 + 255) / 256, 256>>>(b1);
    k_gemm2       <<<(NN + 255) / 256, 256>>>(W2);
    k_agg2h       <<<(NN * 4 + 255) / 256, 256>>>(b2, Wl, bl, out);
}

// round 7
// speedup vs baseline: 1.3460x; 1.0027x over previous
#include <cuda_runtime.h>

#define NN 100000
#define NE 3200000
#define DIN 128
#define HD 16
#define SCAN_B 512
#define NSB ((NN + SCAN_B - 1) / SCAN_B)   // 196

// ---- scratch (static __device__, no allocation) ----
__device__ int    g_deg[NN];
__device__ float  g_dis[NN];
__device__ int    g_rowptr[NN + 1];
__device__ int    g_cursor[NN];
__device__ int    g_col[NE];
__device__ int    g_bsum[NSB];
__device__ float4 g_feat1[NN * 4];   // (x@W1) * dis[row]
__device__ float4 g_feat2[NN * 4];   // (h1@W2) * dis[row]

__device__ __forceinline__ void fma4(float s, const float4 w, float4& a) {
    a.x = fmaf(s, w.x, a.x);
    a.y = fmaf(s, w.y, a.y);
    a.z = fmaf(s, w.z, a.z);
    a.w = fmaf(s, w.w, a.w);
}

// packed f32x2 helpers (sm_100+)
#define PACK2(out, v) asm("mov.b64 %0, {%1, %1};" : "=l"(out) : "r"(__float_as_uint(v)))
#define FMA2(acc, a, b) asm("fma.rn.f32x2 %0, %1, %2, %0;" : "+l"(acc) : "l"(a), "l"(b))

// ---- CSR build ----
__global__ void k_zero() {
    int i = blockIdx.x * blockDim.x + threadIdx.x;
    if (i < NN) g_deg[i] = 0;
}

__global__ void k_count(const int4* __restrict__ dst4) {
    int e = blockIdx.x * blockDim.x + threadIdx.x;
    if (e < NE / 4) {
        int4 d = dst4[e];
        atomicAdd(&g_deg[d.x], 1);
        atomicAdd(&g_deg[d.y], 1);
        atomicAdd(&g_deg[d.z], 1);
        atomicAdd(&g_deg[d.w], 1);
    }
}

// per-block sum of degrees + dis[] computation (fused)
__global__ void k_scan_partial() {
    __shared__ int sh[SCAN_B];
    int i = blockIdx.x * SCAN_B + threadIdx.x;
    int d = (i < NN) ? g_deg[i] : 0;
    if (i < NN) g_dis[i] = rsqrtf((float)(d + 1));  // +1 self-loop
    sh[threadIdx.x] = d;
    __syncthreads();
    for (int off = SCAN_B / 2; off > 0; off >>= 1) {
        if (threadIdx.x < off) sh[threadIdx.x] += sh[threadIdx.x + off];
        __syncthreads();
    }
    if (threadIdx.x == 0) g_bsum[blockIdx.x] = sh[0];
}

// per-block exclusive scan; block offset computed in-kernel (no serial pass)
__global__ void k_scan_final() {
    __shared__ int sh[SCAN_B];
    __shared__ int red[SCAN_B];
    int tid = threadIdx.x;
    int i = blockIdx.x * SCAN_B + tid;
    int v = (i < NN) ? g_deg[i] : 0;
    sh[tid]  = v;
    red[tid] = (tid < blockIdx.x && tid < NSB) ? g_bsum[tid] : 0;
    __syncthreads();
    for (int off = SCAN_B / 2; off > 0; off >>= 1) {
        if (tid < off) red[tid] += red[tid + off];
        __syncthreads();
    }
    for (int off = 1; off < SCAN_B; off <<= 1) {
        int t = (tid >= off) ? sh[tid - off] : 0;
        __syncthreads();
        sh[tid] += t;
        __syncthreads();
    }
    int excl = red[0] + sh[tid] - v;  // exclusive prefix
    if (i < NN) { g_rowptr[i] = excl; g_cursor[i] = excl; }
    if (i == 0) g_rowptr[NN] = NE;
}

__global__ void k_fill(const int4* __restrict__ src4,
                       const int4* __restrict__ dst4) {
    int e = blockIdx.x * blockDim.x + threadIdx.x;
    if (e < NE / 4) {
        int4 s = src4[e];
        int4 d = dst4[e];
        g_col[atomicAdd(&g_cursor[d.x], 1)] = s.x;
        g_col[atomicAdd(&g_cursor[d.y], 1)] = s.y;
        g_col[atomicAdd(&g_cursor[d.z], 1)] = s.z;
        g_col[atomicAdd(&g_cursor[d.w], 1)] = s.w;
    }
}

// ---- gemm1 (packed f32x2): feat1[row] = (x[row] @ W1) * dis[row] ----
__global__ void k_gemm1(const float* __restrict__ x,
                        const float* __restrict__ W1) {
    __shared__ float4 w4[DIN * HD / 4];  // 512 float4 = 8KB; row k at w4[k*4..k*4+3]
    for (int t = threadIdx.x; t < DIN * HD / 4; t += blockDim.x)
        w4[t] = ((const float4*)W1)[t];
    __syncthreads();

    int row = blockIdx.x * blockDim.x + threadIdx.x;
    if (row >= NN) return;

    unsigned long long acc[8];
    #pragma unroll
    for (int i = 0; i < 8; i++) {
        unsigned long long z; PACK2(z, 0.0f); acc[i] = z;
    }

    const float4* xr = (const float4*)(x + (size_t)row * DIN);
    const unsigned long long* w2p = (const unsigned long long*)w4;  // 8B pairs
    #pragma unroll 4
    for (int kk = 0; kk < DIN / 4; kk++) {
        float4 xv = xr[kk];
        float xs[4] = {xv.x, xv.y, xv.z, xv.w};
        #pragma unroll
        for (int c = 0; c < 4; c++) {
            unsigned long long xb; PACK2(xb, xs[c]);
            const unsigned long long* wr = &w2p[(kk * 4 + c) * 8];
            #pragma unroll
            for (int i = 0; i < 8; i++) FMA2(acc[i], xb, wr[i]);
        }
    }

    float s = g_dis[row];
    float o[16];
    #pragma unroll
    for (int i = 0; i < 8; i++) {
        unsigned int lo, hi;
        asm("mov.b64 {%0, %1}, %2;" : "=r"(lo), "=r"(hi) : "l"(acc[i]));
        o[2 * i]     = __uint_as_float(lo) * s;
        o[2 * i + 1] = __uint_as_float(hi) * s;
    }
    float4* fp = &g_feat1[row * 4];
    fp[0] = make_float4(o[0],  o[1],  o[2],  o[3]);
    fp[1] = make_float4(o[4],  o[5],  o[6],  o[7]);
    fp[2] = make_float4(o[8],  o[9],  o[10], o[11]);
    fp[3] = make_float4(o[12], o[13], o[14], o[15]);
}

// ---- fused: agg1 (4 lanes/node) + relu + gemm2 (shuffle) + scale -> feat2 ----
// No early return: out-of-range lanes clamp to node NN-1 (redundant work) so all
// warps stay converged for the shuffles; stores are predicated.
__global__ void k_agg1g2(const float* __restrict__ b1,
                         const float* __restrict__ W2) {
    __shared__ float4 w4[HD * HD / 4];  // W2 row k cols 4q..4q+3 at w4[k*4+q]
    for (int t = threadIdx.x; t < HD * HD / 4; t += blockDim.x)
        w4[t] = ((const float4*)W2)[t];
    __syncthreads();

    int t = blockIdx.x * blockDim.x + threadIdx.x;
    int node0 = t >> 2, q = t & 3;
    int node = node0 < NN ? node0 : NN - 1;

    float4 acc = g_feat1[node * 4 + q];  // self-loop term
    int s = g_rowptr[node], e = g_rowptr[node + 1];
    for (int j = s; j < e; j++) {
        int c = g_col[j];
        float4 v = g_feat1[c * 4 + q];
        acc.x += v.x; acc.y += v.y; acc.z += v.z; acc.w += v.w;
    }
    float ds = g_dis[node];
    float4 bb = ((const float4*)b1)[q];
    float h[4];
    h[0] = fmaxf(fmaf(acc.x, ds, bb.x), 0.f);
    h[1] = fmaxf(fmaf(acc.y, ds, bb.y), 0.f);
    h[2] = fmaxf(fmaf(acc.z, ds, bb.z), 0.f);
    h[3] = fmaxf(fmaf(acc.w, ds, bb.w), 0.f);

    // gemm2: o[4q..4q+3] = sum_k h_all[k] * W2[k][4q..4q+3]
    float4 o = {0.f, 0.f, 0.f, 0.f};
    #pragma unroll
    for (int k = 0; k < HD; k++) {
        float hk = __shfl_sync(0xffffffffu, h[k & 3], k >> 2, 4);
        fma4(hk, w4[k * 4 + q], o);
    }
    o.x *= ds; o.y *= ds; o.z *= ds; o.w *= ds;
    if (node0 < NN) g_feat2[node0 * 4 + q] = o;
}

// ---- aggregation layer 2 + fused linear head (4 lanes per node) ----
__global__ void k_agg2h(const float* __restrict__ b2,
                        const float* __restrict__ Wl,
                        const float* __restrict__ bl,
                        float* __restrict__ out) {
    int t = blockIdx.x * blockDim.x + threadIdx.x;
    int node0 = t >> 2, q = t & 3;
    int node = node0 < NN ? node0 : NN - 1;

    float4 acc = g_feat2[node * 4 + q];  // self loop
    int s = g_rowptr[node], e = g_rowptr[node + 1];
    for (int j = s; j < e; j++) {
        int c = g_col[j];
        float4 v = g_feat2[c * 4 + q];
        acc.x += v.x; acc.y += v.y; acc.z += v.z; acc.w += v.w;
    }
    float ds = g_dis[node];
    float4 bb = ((const float4*)b2)[q];
    float4 wl = ((const float4*)Wl)[q];
    float p = fmaxf(fmaf(acc.x, ds, bb.x), 0.f) * wl.x
            + fmaxf(fmaf(acc.y, ds, bb.y), 0.f) * wl.y
            + fmaxf(fmaf(acc.z, ds, bb.z), 0.f) * wl.z
            + fmaxf(fmaf(acc.w, ds, bb.w), 0.f) * wl.w;
    p += __shfl_xor_sync(0xffffffffu, p, 1, 4);
    p += __shfl_xor_sync(0xffffffffu, p, 2, 4);
    if (q == 0 && node0 < NN) out[node0] = p + bl[0];
}

extern "C" void kernel_launch(void* const* d_in, const int* in_sizes, int n_in,
                              void* d_out, int out_size) {
    const float* x  = (const float*)d_in[0];
    const int*   ei = (const int*)d_in[1];    // int32 (JAX x64 disabled)
    const float* W1 = (const float*)d_in[2];
    const float* b1 = (const float*)d_in[3];
    const float* W2 = (const float*)d_in[4];
    const float* b2 = (const float*)d_in[5];
    const float* Wl = (const float*)d_in[6];
    const float* bl = (const float*)d_in[7];
    float* out = (float*)d_out;

    const int4* src4 = (const int4*)ei;          // edge_index[0]
    const int4* dst4 = (const int4*)(ei + NE);   // edge_index[1]

    k_zero        <<<(NN + 255) / 256, 256>>>();
    k_count       <<<(NE / 4 + 255) / 256, 256>>>(dst4);
    k_scan_partial<<<NSB, SCAN_B>>>();
    k_scan_final  <<<NSB, SCAN_B>>>();
    k_fill        <<<(NE / 4 + 255) / 256, 256>>>(src4, dst4);
    k_gemm1       <<<(NN + 255) / 256, 256>>>(x, W1);
    k_agg1g2      <<<(NN * 4 + 255) / 256, 256>>>(b1, W2);
    k_agg2h       <<<(NN * 4 + 255) / 256, 256>>>(b2, Wl, bl, out);
}

// round 10
// speedup vs baseline: 1.5485x; 1.1504x over previous
#include <cuda_runtime.h>

#define NN 100000
#define NE 3200000
#define DIN 128
#define HD 16
#define SCAN_B 512
#define NSB ((NN + SCAN_B - 1) / SCAN_B)   // 196

// ---- scratch (static __device__, no allocation) ----
__device__ int    g_deg[NN];
__device__ float  g_dis[NN];
__device__ int    g_rowptr[NN + 1];
__device__ int    g_cursor[NN];
__device__ int    g_col[NE];
__device__ int    g_bsum[NSB];
__device__ float4 g_feat1[NN * 4];   // (x@W1) * dis[row]
__device__ float4 g_feat2[NN * 4];   // (h1@W2) * dis[row]

// packed f32x2 helpers (sm_100+)
#define PACK2(out, v) asm("mov.b64 %0, {%1, %1};" : "=l"(out) : "r"(__float_as_uint(v)))
#define FMA2(acc, a, b) asm("fma.rn.f32x2 %0, %1, %2, %0;" : "+l"(acc) : "l"(a), "l"(b))

// ---- CSR build ----
__global__ void k_zero() {
    int i = blockIdx.x * blockDim.x + threadIdx.x;
    if (i < NN) g_deg[i] = 0;
}

__global__ void k_count(const int4* __restrict__ dst4) {
    int e = blockIdx.x * blockDim.x + threadIdx.x;
    if (e < NE / 4) {
        int4 d = dst4[e];
        atomicAdd(&g_deg[d.x], 1);
        atomicAdd(&g_deg[d.y], 1);
        atomicAdd(&g_deg[d.z], 1);
        atomicAdd(&g_deg[d.w], 1);
    }
}

// per-block sum of degrees + dis[] computation (fused)
__global__ void k_scan_partial() {
    __shared__ int sh[SCAN_B];
    int i = blockIdx.x * SCAN_B + threadIdx.x;
    int d = (i < NN) ? g_deg[i] : 0;
    if (i < NN) g_dis[i] = rsqrtf((float)(d + 1));  // +1 self-loop
    sh[threadIdx.x] = d;
    __syncthreads();
    for (int off = SCAN_B / 2; off > 0; off >>= 1) {
        if (threadIdx.x < off) sh[threadIdx.x] += sh[threadIdx.x + off];
        __syncthreads();
    }
    if (threadIdx.x == 0) g_bsum[blockIdx.x] = sh[0];
}

// per-block exclusive scan; block offset computed in-kernel (no serial pass)
__global__ void k_scan_final() {
    __shared__ int sh[SCAN_B];
    __shared__ int red[SCAN_B];
    int tid = threadIdx.x;
    int i = blockIdx.x * SCAN_B + tid;
    int v = (i < NN) ? g_deg[i] : 0;
    sh[tid]  = v;
    red[tid] = (tid < blockIdx.x && tid < NSB) ? g_bsum[tid] : 0;
    __syncthreads();
    for (int off = SCAN_B / 2; off > 0; off >>= 1) {
        if (tid < off) red[tid] += red[tid + off];
        __syncthreads();
    }
    for (int off = 1; off < SCAN_B; off <<= 1) {
        int t = (tid >= off) ? sh[tid - off] : 0;
        __syncthreads();
        sh[tid] += t;
        __syncthreads();
    }
    int excl = red[0] + sh[tid] - v;  // exclusive prefix
    if (i < NN) { g_rowptr[i] = excl; g_cursor[i] = excl; }
    if (i == 0) g_rowptr[NN] = NE;
}

__global__ void k_fill(const int4* __restrict__ src4,
                       const int4* __restrict__ dst4) {
    int e = blockIdx.x * blockDim.x + threadIdx.x;
    if (e < NE / 4) {
        int4 s = src4[e];
        int4 d = dst4[e];
        g_col[atomicAdd(&g_cursor[d.x], 1)] = s.x;
        g_col[atomicAdd(&g_cursor[d.y], 1)] = s.y;
        g_col[atomicAdd(&g_cursor[d.z], 1)] = s.z;
        g_col[atomicAdd(&g_cursor[d.w], 1)] = s.w;
    }
}

// ---- gemm1 (packed f32x2): feat1[row] = (x[row] @ W1) * dis[row] ----
__global__ void k_gemm1(const float* __restrict__ x,
                        const float* __restrict__ W1) {
    __shared__ float4 w4[DIN * HD / 4];  // 8KB; row k at w4[k*4..k*4+3]
    for (int t = threadIdx.x; t < DIN * HD / 4; t += blockDim.x)
        w4[t] = ((const float4*)W1)[t];
    __syncthreads();

    int row = blockIdx.x * blockDim.x + threadIdx.x;
    if (row >= NN) return;

    unsigned long long acc[8];
    #pragma unroll
    for (int i = 0; i < 8; i++) {
        unsigned long long z; PACK2(z, 0.0f); acc[i] = z;
    }

    const float4* xr = (const float4*)(x + (size_t)row * DIN);
    const unsigned long long* w2p = (const unsigned long long*)w4;
    #pragma unroll 4
    for (int kk = 0; kk < DIN / 4; kk++) {
        float4 xv = xr[kk];
        float xs[4] = {xv.x, xv.y, xv.z, xv.w};
        #pragma unroll
        for (int c = 0; c < 4; c++) {
            unsigned long long xb; PACK2(xb, xs[c]);
            const unsigned long long* wr = &w2p[(kk * 4 + c) * 8];
            #pragma unroll
            for (int i = 0; i < 8; i++) FMA2(acc[i], xb, wr[i]);
        }
    }

    float s = g_dis[row];
    float o[16];
    #pragma unroll
    for (int i = 0; i < 8; i++) {
        unsigned int lo, hi;
        asm("mov.b64 {%0, %1}, %2;" : "=r"(lo), "=r"(hi) : "l"(acc[i]));
        o[2 * i]     = __uint_as_float(lo) * s;
        o[2 * i + 1] = __uint_as_float(hi) * s;
    }
    float4* fp = &g_feat1[row * 4];
    fp[0] = make_float4(o[0],  o[1],  o[2],  o[3]);
    fp[1] = make_float4(o[4],  o[5],  o[6],  o[7]);
    fp[2] = make_float4(o[8],  o[9],  o[10], o[11]);
    fp[3] = make_float4(o[12], o[13], o[14], o[15]);
}

// ---- fused: agg1 (8 lanes/node) + relu + gemm2 (width-8 shuffle) -> feat2 ----
// No early return: out-of-range lanes clamp to node NN-1 so all warps stay
// converged for the shuffles; stores are predicated.
__global__ void k_agg1g2(const float* __restrict__ b1,
                         const float* __restrict__ W2) {
    __shared__ float2 w2s[HD * HD / 2];  // [k*8+q] = W2[k][2q..2q+1]
    for (int t = threadIdx.x; t < HD * HD / 2; t += blockDim.x)
        w2s[t] = ((const float2*)W2)[t];
    __syncthreads();

    int t = blockIdx.x * blockDim.x + threadIdx.x;
    int node0 = t >> 3, q = t & 7;
    int node = node0 < NN ? node0 : NN - 1;

    const float2* f1 = (const float2*)g_feat1;
    float2 acc = f1[node * 8 + q];  // self-loop term
    int s = g_rowptr[node], e = g_rowptr[node + 1];
    #pragma unroll 2
    for (int j = s; j < e; j++) {
        float2 v = f1[g_col[j] * 8 + q];
        acc.x += v.x; acc.y += v.y;
    }
    float ds = g_dis[node];
    float2 bb = ((const float2*)b1)[q];
    float h[2];
    h[0] = fmaxf(fmaf(acc.x, ds, bb.x), 0.f);
    h[1] = fmaxf(fmaf(acc.y, ds, bb.y), 0.f);

    // gemm2: o[2q..2q+1] = sum_k h_all[k] * W2[k][2q..2q+1]
    float2 o = {0.f, 0.f};
    #pragma unroll
    for (int k = 0; k < HD; k++) {
        float hk = __shfl_sync(0xffffffffu, h[k & 1], k >> 1, 8);
        float2 w = w2s[k * 8 + q];
        o.x = fmaf(hk, w.x, o.x);
        o.y = fmaf(hk, w.y, o.y);
    }
    o.x *= ds; o.y *= ds;
    if (node0 < NN) ((float2*)g_feat2)[node0 * 8 + q] = o;
}

// ---- agg2 (8 lanes/node) + relu + fused linear head ----
__global__ void k_agg2h(const float* __restrict__ b2,
                        const float* __restrict__ Wl,
                        const float* __restrict__ bl,
                        float* __restrict__ out) {
    int t = blockIdx.x * blockDim.x + threadIdx.x;
    int node0 = t >> 3, q = t & 7;
    int node = node0 < NN ? node0 : NN - 1;

    const float2* f2 = (const float2*)g_feat2;
    float2 acc = f2[node * 8 + q];  // self-loop term
    int s = g_rowptr[node], e = g_rowptr[node + 1];
    #pragma unroll 2
    for (int j = s; j < e; j++) {
        float2 v = f2[g_col[j] * 8 + q];
        acc.x += v.x; acc.y += v.y;
    }
    float ds = g_dis[node];
    float2 bb = ((const float2*)b2)[q];
    float2 wl = ((const float2*)Wl)[q];
    float p = fmaxf(fmaf(acc.x, ds, bb.x), 0.f) * wl.x
            + fmaxf(fmaf(acc.y, ds, bb.y), 0.f) * wl.y;
    p += __shfl_xor_sync(0xffffffffu, p, 1, 8);
    p += __shfl_xor_sync(0xffffffffu, p, 2, 8);
    p += __shfl_xor_sync(0xffffffffu, p, 4, 8);
    if (q == 0 && node0 < NN) out[node0] = p + bl[0];
}

extern "C" void kernel_launch(void* const* d_in, const int* in_sizes, int n_in,
                              void* d_out, int out_size) {
    const float* x  = (const float*)d_in[0];
    const int*   ei = (const int*)d_in[1];    // int32 (JAX x64 disabled)
    const float* W1 = (const float*)d_in[2];
    const float* b1 = (const float*)d_in[3];
    const float* W2 = (const float*)d_in[4];
    const float* b2 = (const float*)d_in[5];
    const float* Wl = (const float*)d_in[6];
    const float* bl = (const float*)d_in[7];
    float* out = (float*)d_out;

    const int4* src4 = (const int4*)ei;          // edge_index[0]
    const int4* dst4 = (const int4*)(ei + NE);   // edge_index[1]

    // one-time stream/event setup (outside capture; does not change per-call work)
    static cudaStream_t s2 = nullptr;
    static cudaEvent_t evF = nullptr, evJ = nullptr;
    if (s2 == nullptr) {
        cudaStreamCreateWithFlags(&s2, cudaStreamNonBlocking);
        cudaEventCreateWithFlags(&evF, cudaEventDisableTiming);
        cudaEventCreateWithFlags(&evJ, cudaEventDisableTiming);
    }

    k_zero        <<<(NN + 255) / 256, 256>>>();
    k_count       <<<(NE / 4 + 255) / 256, 256>>>(dst4);
    k_scan_partial<<<NSB, SCAN_B>>>();

    // fork: gemm1 depends only on g_dis (ready after scan_partial)
    cudaEventRecord(evF, 0);
    cudaStreamWaitEvent(s2, evF, 0);
    k_gemm1<<<(NN + 255) / 256, 256, 0, s2>>>(x, W1);
    cudaEventRecord(evJ, s2);

    k_scan_final  <<<NSB, SCAN_B>>>();
    k_fill        <<<(NE / 4 + 255) / 256, 256>>>(src4, dst4);

    // join: agg1g2 needs both CSR (main stream) and feat1 (s2)
    cudaStreamWaitEvent(0, evJ, 0);
    k_agg1g2      <<<(NN * 8 + 255) / 256, 256>>>(b1, W2);
    k_agg2h       <<<(NN * 8 + 255) / 256, 256>>>(b2, Wl, bl, out);
}